// round 6
// baseline (speedup 1.0000x reference)
#include <cuda_runtime.h>
#include <math.h>

#define MAXN 50000
#define MAXE 800000
#define FDIM 128

// Scratch (__device__ globals: allocation-free per harness rules)
__device__ __align__(16) float g_h[MAXN * FDIM];    // h = A @ W
__device__ __align__(16) float g_agg[MAXN * FDIM];  // layer output
__device__ __align__(16) float g_dinv[MAXN];
__device__ __align__(16) float g_z[MAXN];
__device__ int g_src[MAXE];
__device__ int g_dst[MAXE];
__device__ int g_csr_src[MAXE];
__device__ int g_cnt[MAXN];
__device__ int g_cur[MAXN];
__device__ int g_rowptr[MAXN + 1];
__device__ int g_bsum[64];
__device__ int g_boff[64];
__device__ int g_is64;

// ---------------------------------------------------------------------------
// Fused: zero in-degree counters + edge dtype detection (block 0)
// ---------------------------------------------------------------------------
__global__ void k_init(const int* __restrict__ w, int N) {
    int i = blockIdx.x * blockDim.x + threadIdx.x;
    if (i < N) g_cnt[i] = 0;
    if (blockIdx.x == 0) {
        __shared__ int any;
        if (threadIdx.x == 0) any = 0;
        __syncthreads();
        int idx = 2 * threadIdx.x + 1;       // odd int32 words of edge buffer
        if (idx < 512 && w[idx] != 0) any = 1;
        __syncthreads();
        if (threadIdx.x == 0) g_is64 = (any == 0);
    }
}

// Convert edges to int32 arrays + count in-degree
__global__ void k_convert_count(const void* __restrict__ ei, int E, int N) {
    int e = blockIdx.x * blockDim.x + threadIdx.x;
    if (e >= E) return;
    int s, d;
    if (g_is64) {
        const long long* p = (const long long*)ei;
        s = (int)p[e]; d = (int)p[E + e];
    } else {
        const int* p = (const int*)ei;
        s = p[e]; d = p[E + e];
    }
    g_src[e] = s;
    g_dst[e] = d;
    if ((unsigned)d < (unsigned)N) atomicAdd(&g_cnt[d], 1);
}

// ---------------------------------------------------------------------------
// Parallel 3-phase exclusive scan of g_cnt -> g_rowptr
// ---------------------------------------------------------------------------
__global__ void __launch_bounds__(1024) k_scan1(int N) {
    __shared__ int sh[1024];
    int t = threadIdx.x;
    int i = blockIdx.x * 1024 + t;
    int c = (i < N) ? g_cnt[i] : 0;
    sh[t] = c;
    __syncthreads();
#pragma unroll
    for (int off = 1; off < 1024; off <<= 1) {
        int v = (t >= off) ? sh[t - off] : 0;
        __syncthreads();
        sh[t] += v;
        __syncthreads();
    }
    if (i < N) {
        g_rowptr[i] = sh[t] - c;
        g_dinv[i] = rsqrtf(1.0f + (float)c);
        g_cur[i] = 0;
    }
    if (t == 1023) g_bsum[blockIdx.x] = sh[1023];
}

__global__ void __launch_bounds__(64) k_scan2(int nb, int N) {
    __shared__ int sh[64];
    int t = threadIdx.x;
    int v = (t < nb) ? g_bsum[t] : 0;
    sh[t] = v;
    __syncthreads();
#pragma unroll
    for (int off = 1; off < 64; off <<= 1) {
        int u = (t >= off) ? sh[t - off] : 0;
        __syncthreads();
        sh[t] += u;
        __syncthreads();
    }
    if (t < nb) g_boff[t] = sh[t] - v;
    if (t == 63) g_rowptr[N] = sh[63];
}

__global__ void __launch_bounds__(1024) k_scan3(int N) {
    int i = blockIdx.x * 1024 + threadIdx.x;
    if (i < N) g_rowptr[i] += g_boff[blockIdx.x];
}

__global__ void k_fill(int E, int N) {
    int e = blockIdx.x * blockDim.x + threadIdx.x;
    if (e >= E) return;
    int s = g_src[e];
    int d = g_dst[e];
    if ((unsigned)s >= (unsigned)N || (unsigned)d >= (unsigned)N) return;
    int pos = g_rowptr[d] + atomicAdd(&g_cur[d], 1);
    g_csr_src[pos] = s;
}

// ---------------------------------------------------------------------------
// GEMM: g_h[N,128] = A[N,128] @ W[128,128]
// MODE 0: A = concat(x_i, x_j); MODE 1: A = relu(g_agg)
// ---------------------------------------------------------------------------
template <int MODE>
__global__ void __launch_bounds__(128)
k_gemm(const float* __restrict__ A0, const float* __restrict__ A1,
       const float* __restrict__ W, int N)
{
    __shared__ float As[16][64];
    __shared__ float Bs[16][128];

    const int tid = threadIdx.x;
    const int tmb = (tid >> 4) * 8;
    const int tnb = (tid & 15) * 8;
    const int rowBase = blockIdx.x * 64;

    float acc[8][8];
#pragma unroll
    for (int i = 0; i < 8; i++)
#pragma unroll
        for (int j = 0; j < 8; j++) acc[i][j] = 0.0f;

    for (int kk = 0; kk < 128; kk += 16) {
#pragma unroll
        for (int t = 0; t < 2; t++) {
            int id = tid * 2 + t;
            int r = id >> 2, c4 = id & 3;
            int grow = rowBase + r;
            int gcol = kk + c4 * 4;
            float4 v = make_float4(0.f, 0.f, 0.f, 0.f);
            if (grow < N) {
                if (MODE == 0) {
                    const float* base = (gcol < 64)
                        ? (A0 + (size_t)grow * 64 + gcol)
                        : (A1 + (size_t)grow * 64 + (gcol - 64));
                    v = *(const float4*)base;
                } else {
                    v = *(const float4*)(g_agg + (size_t)grow * 128 + gcol);
                    v.x = fmaxf(v.x, 0.f); v.y = fmaxf(v.y, 0.f);
                    v.z = fmaxf(v.z, 0.f); v.w = fmaxf(v.w, 0.f);
                }
            }
            As[c4 * 4 + 0][r] = v.x;
            As[c4 * 4 + 1][r] = v.y;
            As[c4 * 4 + 2][r] = v.z;
            As[c4 * 4 + 3][r] = v.w;
        }
#pragma unroll
        for (int t = 0; t < 4; t++) {
            int id = tid * 4 + t;
            int k = id >> 5, c4 = id & 31;
            float4 v = *(const float4*)(W + (size_t)(kk + k) * 128 + c4 * 4);
            *(float4*)&Bs[k][c4 * 4] = v;
        }
        __syncthreads();

#pragma unroll
        for (int k = 0; k < 16; k++) {
            float a[8], b[8];
            *(float4*)&a[0] = *(const float4*)&As[k][tmb];
            *(float4*)&a[4] = *(const float4*)&As[k][tmb + 4];
            *(float4*)&b[0] = *(const float4*)&Bs[k][tnb];
            *(float4*)&b[4] = *(const float4*)&Bs[k][tnb + 4];
#pragma unroll
            for (int i = 0; i < 8; i++)
#pragma unroll
                for (int j = 0; j < 8; j++)
                    acc[i][j] = fmaf(a[i], b[j], acc[i][j]);
        }
        __syncthreads();
    }

#pragma unroll
    for (int i = 0; i < 8; i++) {
        int row = rowBase + tmb + i;
        if (row >= N) continue;
#pragma unroll
        for (int j = 0; j < 8; j += 4) {
            int col = tnb + j;
            float4 h = make_float4(acc[i][j], acc[i][j + 1], acc[i][j + 2], acc[i][j + 3]);
            *(float4*)(g_h + (size_t)row * 128 + col) = h;
        }
    }
}

// ---------------------------------------------------------------------------
// CSR aggregation: one warp per dst node, 4-edge unrolled (MLP).
// EPI 0: store row to g_agg.
// EPI 1: z[d] = dot(relu(row), W3) -> g_z   (fused layer-3 projection)
// ---------------------------------------------------------------------------
template <int EPI>
__global__ void __launch_bounds__(256)
k_agg(const float* __restrict__ bias, const float* __restrict__ W3, int N)
{
    int idx = blockIdx.x * blockDim.x + threadIdx.x;
    int d = idx >> 5;
    int lane = idx & 31;
    if (d >= N) return;

    const float dd = g_dinv[d];
    const int col = lane * 4;
    const unsigned FULL = 0xffffffffu;

    // self-loop + bias
    float4 hv = *(const float4*)(g_h + (size_t)d * 128 + col);
    float4 bb = *(const float4*)(bias + col);
    float d2 = dd * dd;
    float4 a0 = make_float4(fmaf(hv.x, d2, bb.x), fmaf(hv.y, d2, bb.y),
                            fmaf(hv.z, d2, bb.z), fmaf(hv.w, d2, bb.w));
    float4 a1 = make_float4(0.f, 0.f, 0.f, 0.f);
    float4 a2 = make_float4(0.f, 0.f, 0.f, 0.f);
    float4 a3 = make_float4(0.f, 0.f, 0.f, 0.f);

    int beg = g_rowptr[d];
    int end = g_rowptr[d + 1];
    for (int p = beg; p < end; p += 32) {
        int m = end - p;
        if (m > 32) m = 32;
        int s = 0;
        float ns = 0.0f;
        if (lane < m) {
            s = g_csr_src[p + lane];
            ns = g_dinv[s];
        }
        int j = 0;
        for (; j + 4 <= m; j += 4) {
            int s0 = __shfl_sync(FULL, s, j);
            int s1 = __shfl_sync(FULL, s, j + 1);
            int s2 = __shfl_sync(FULL, s, j + 2);
            int s3 = __shfl_sync(FULL, s, j + 3);
            float n0 = __shfl_sync(FULL, ns, j) * dd;
            float n1 = __shfl_sync(FULL, ns, j + 1) * dd;
            float n2 = __shfl_sync(FULL, ns, j + 2) * dd;
            float n3 = __shfl_sync(FULL, ns, j + 3) * dd;
            float4 v0 = *(const float4*)(g_h + (size_t)s0 * 128 + col);
            float4 v1 = *(const float4*)(g_h + (size_t)s1 * 128 + col);
            float4 v2 = *(const float4*)(g_h + (size_t)s2 * 128 + col);
            float4 v3 = *(const float4*)(g_h + (size_t)s3 * 128 + col);
            a0.x = fmaf(v0.x, n0, a0.x); a0.y = fmaf(v0.y, n0, a0.y);
            a0.z = fmaf(v0.z, n0, a0.z); a0.w = fmaf(v0.w, n0, a0.w);
            a1.x = fmaf(v1.x, n1, a1.x); a1.y = fmaf(v1.y, n1, a1.y);
            a1.z = fmaf(v1.z, n1, a1.z); a1.w = fmaf(v1.w, n1, a1.w);
            a2.x = fmaf(v2.x, n2, a2.x); a2.y = fmaf(v2.y, n2, a2.y);
            a2.z = fmaf(v2.z, n2, a2.z); a2.w = fmaf(v2.w, n2, a2.w);
            a3.x = fmaf(v3.x, n3, a3.x); a3.y = fmaf(v3.y, n3, a3.y);
            a3.z = fmaf(v3.z, n3, a3.z); a3.w = fmaf(v3.w, n3, a3.w);
        }
        for (; j < m; j++) {
            int sj = __shfl_sync(FULL, s, j);
            float nj = __shfl_sync(FULL, ns, j) * dd;
            float4 v = *(const float4*)(g_h + (size_t)sj * 128 + col);
            a0.x = fmaf(v.x, nj, a0.x); a0.y = fmaf(v.y, nj, a0.y);
            a0.z = fmaf(v.z, nj, a0.z); a0.w = fmaf(v.w, nj, a0.w);
        }
    }
    float4 acc = make_float4(a0.x + a1.x + a2.x + a3.x,
                             a0.y + a1.y + a2.y + a3.y,
                             a0.z + a1.z + a2.z + a3.z,
                             a0.w + a1.w + a2.w + a3.w);
    if (EPI == 0) {
        *(float4*)(g_agg + (size_t)d * 128 + col) = acc;
    } else {
        acc.x = fmaxf(acc.x, 0.f); acc.y = fmaxf(acc.y, 0.f);
        acc.z = fmaxf(acc.z, 0.f); acc.w = fmaxf(acc.w, 0.f);
        float4 w = *(const float4*)(W3 + col);
        float sdot = acc.x * w.x + acc.y * w.y + acc.z * w.z + acc.w * w.w;
#pragma unroll
        for (int o = 16; o > 0; o >>= 1) sdot += __shfl_xor_sync(FULL, sdot, o);
        if (lane == 0) g_z[d] = sdot;
    }
}

// Final: out[d] = sigmoid(z[d]*dd^2 + b3 + dd * sum_in z[s]*dinv[s])
__global__ void __launch_bounds__(256)
k_agg3(const float* __restrict__ b3, float* __restrict__ out, int N)
{
    int idx = blockIdx.x * blockDim.x + threadIdx.x;
    int d = idx >> 5;
    int lane = idx & 31;
    if (d >= N) return;
    int beg = g_rowptr[d];
    int end = g_rowptr[d + 1];
    float sum = 0.0f;
    for (int p = beg + lane; p < end; p += 32) {
        int s = g_csr_src[p];
        sum = fmaf(g_z[s], g_dinv[s], sum);
    }
#pragma unroll
    for (int o = 16; o > 0; o >>= 1) sum += __shfl_xor_sync(0xffffffffu, sum, o);
    if (lane == 0) {
        float dd = g_dinv[d];
        float val = fmaf(g_z[d], dd * dd, fmaf(dd, sum, b3[0]));
        out[d] = 1.0f / (1.0f + expf(-val));
    }
}

// ---------------------------------------------------------------------------
extern "C" void kernel_launch(void* const* d_in, const int* in_sizes, int n_in,
                              void* d_out, int out_size)
{
    const float* x_i = (const float*)d_in[0];
    const float* x_j = (const float*)d_in[1];
    const void*  ei  = d_in[2];
    const float* W1 = (const float*)d_in[3];
    const float* b1 = (const float*)d_in[4];
    const float* W2 = (const float*)d_in[5];
    const float* b2 = (const float*)d_in[6];
    const float* W3 = (const float*)d_in[7];
    const float* b3 = (const float*)d_in[8];
    float* out = (float*)d_out;

    const int N = in_sizes[0] / 64;
    const int E = in_sizes[2] / 2;

    const int TB = 256;
    const int NB = (N + 1023) / 1024;
    dim3 gN((N + TB - 1) / TB);
    dim3 gE((E + TB - 1) / TB);
    dim3 gGemm((N + 63) / 64);
    dim3 gWarpN((unsigned)(((long long)N * 32 + TB - 1) / TB));

    // CSR build (launches 0-4), then gemm<0> as launch #5 for ncu -s 5
    k_init<<<gN, TB>>>((const int*)ei, N);
    k_convert_count<<<gE, TB>>>(ei, E, N);
    k_scan1<<<NB, 1024>>>(N);
    k_scan2<<<1, 64>>>(NB, N);
    k_scan3<<<NB, 1024>>>(N);

    // layer 1 GEMM (independent of fill; fill ordered after for profiling)
    k_gemm<0><<<gGemm, 128>>>(x_i, x_j, W1, N);
    k_fill<<<gE, TB>>>(E, N);
    k_agg<0><<<gWarpN, TB>>>(b1, nullptr, N);

    // layer 2 (z fused into agg epilogue)
    k_gemm<1><<<gGemm, 128>>>(nullptr, nullptr, W2, N);
    k_agg<1><<<gWarpN, TB>>>(b2, W3, N);

    // layer 3 final
    k_agg3<<<gWarpN, TB>>>(b3, out, N);
}

// round 7
// speedup vs baseline: 1.1384x; 1.1384x over previous
#include <cuda_runtime.h>
#include <cuda_fp16.h>
#include <math.h>

#define MAXN 50000
#define MAXE 800000
#define FDIM 128

// Scratch (__device__ globals: allocation-free per harness rules)
__device__ __align__(16) __half g_h[MAXN * FDIM];   // h = A @ W  (fp16 storage)
__device__ __align__(16) float g_agg[MAXN * FDIM];  // layer output (fp32)
__device__ __align__(16) float g_dinv[MAXN];
__device__ __align__(16) float g_z[MAXN];
__device__ int g_src[MAXE];
__device__ int g_dst[MAXE];
__device__ int g_csr_src[MAXE];
__device__ int g_cnt[MAXN];
__device__ int g_cur[MAXN];
__device__ int g_rowptr[MAXN + 1];
__device__ int g_bsum[64];
__device__ int g_boff[64];
__device__ int g_is64;

// ---------------------------------------------------------------------------
// Fused: zero in-degree counters + edge dtype detection (block 0)
// ---------------------------------------------------------------------------
__global__ void k_init(const int* __restrict__ w, int N) {
    int i = blockIdx.x * blockDim.x + threadIdx.x;
    if (i < N) g_cnt[i] = 0;
    if (blockIdx.x == 0) {
        __shared__ int any;
        if (threadIdx.x == 0) any = 0;
        __syncthreads();
        int idx = 2 * threadIdx.x + 1;
        if (idx < 512 && w[idx] != 0) any = 1;
        __syncthreads();
        if (threadIdx.x == 0) g_is64 = (any == 0);
    }
}

__global__ void k_convert_count(const void* __restrict__ ei, int E, int N) {
    int e = blockIdx.x * blockDim.x + threadIdx.x;
    if (e >= E) return;
    int s, d;
    if (g_is64) {
        const long long* p = (const long long*)ei;
        s = (int)p[e]; d = (int)p[E + e];
    } else {
        const int* p = (const int*)ei;
        s = p[e]; d = p[E + e];
    }
    g_src[e] = s;
    g_dst[e] = d;
    if ((unsigned)d < (unsigned)N) atomicAdd(&g_cnt[d], 1);
}

// ---------------------------------------------------------------------------
// Parallel 3-phase exclusive scan of g_cnt -> g_rowptr
// ---------------------------------------------------------------------------
__global__ void __launch_bounds__(1024) k_scan1(int N) {
    __shared__ int sh[1024];
    int t = threadIdx.x;
    int i = blockIdx.x * 1024 + t;
    int c = (i < N) ? g_cnt[i] : 0;
    sh[t] = c;
    __syncthreads();
#pragma unroll
    for (int off = 1; off < 1024; off <<= 1) {
        int v = (t >= off) ? sh[t - off] : 0;
        __syncthreads();
        sh[t] += v;
        __syncthreads();
    }
    if (i < N) {
        g_rowptr[i] = sh[t] - c;
        g_dinv[i] = rsqrtf(1.0f + (float)c);
        g_cur[i] = 0;
    }
    if (t == 1023) g_bsum[blockIdx.x] = sh[1023];
}

__global__ void __launch_bounds__(64) k_scan2(int nb, int N) {
    __shared__ int sh[64];
    int t = threadIdx.x;
    int v = (t < nb) ? g_bsum[t] : 0;
    sh[t] = v;
    __syncthreads();
#pragma unroll
    for (int off = 1; off < 64; off <<= 1) {
        int u = (t >= off) ? sh[t - off] : 0;
        __syncthreads();
        sh[t] += u;
        __syncthreads();
    }
    if (t < nb) g_boff[t] = sh[t] - v;
    if (t == 63) g_rowptr[N] = sh[63];
}

__global__ void __launch_bounds__(1024) k_scan3(int N) {
    int i = blockIdx.x * 1024 + threadIdx.x;
    if (i < N) g_rowptr[i] += g_boff[blockIdx.x];
}

__global__ void k_fill(int E, int N) {
    int e = blockIdx.x * blockDim.x + threadIdx.x;
    if (e >= E) return;
    int s = g_src[e];
    int d = g_dst[e];
    if ((unsigned)s >= (unsigned)N || (unsigned)d >= (unsigned)N) return;
    int pos = g_rowptr[d] + atomicAdd(&g_cur[d], 1);
    g_csr_src[pos] = s;
}

// ---------------------------------------------------------------------------
// GEMM: g_h[N,128] = A[N,128] @ W[128,128]  (fp32 compute, fp16 store)
// MODE 0: A = concat(x_i, x_j); MODE 1: A = relu(g_agg)
// ---------------------------------------------------------------------------
template <int MODE>
__global__ void __launch_bounds__(128)
k_gemm(const float* __restrict__ A0, const float* __restrict__ A1,
       const float* __restrict__ W, int N)
{
    __shared__ float As[16][64];
    __shared__ float Bs[16][128];

    const int tid = threadIdx.x;
    const int tmb = (tid >> 4) * 8;
    const int tnb = (tid & 15) * 8;
    const int rowBase = blockIdx.x * 64;

    float acc[8][8];
#pragma unroll
    for (int i = 0; i < 8; i++)
#pragma unroll
        for (int j = 0; j < 8; j++) acc[i][j] = 0.0f;

    for (int kk = 0; kk < 128; kk += 16) {
#pragma unroll
        for (int t = 0; t < 2; t++) {
            int id = tid * 2 + t;
            int r = id >> 2, c4 = id & 3;
            int grow = rowBase + r;
            int gcol = kk + c4 * 4;
            float4 v = make_float4(0.f, 0.f, 0.f, 0.f);
            if (grow < N) {
                if (MODE == 0) {
                    const float* base = (gcol < 64)
                        ? (A0 + (size_t)grow * 64 + gcol)
                        : (A1 + (size_t)grow * 64 + (gcol - 64));
                    v = *(const float4*)base;
                } else {
                    v = *(const float4*)(g_agg + (size_t)grow * 128 + gcol);
                    v.x = fmaxf(v.x, 0.f); v.y = fmaxf(v.y, 0.f);
                    v.z = fmaxf(v.z, 0.f); v.w = fmaxf(v.w, 0.f);
                }
            }
            As[c4 * 4 + 0][r] = v.x;
            As[c4 * 4 + 1][r] = v.y;
            As[c4 * 4 + 2][r] = v.z;
            As[c4 * 4 + 3][r] = v.w;
        }
#pragma unroll
        for (int t = 0; t < 4; t++) {
            int id = tid * 4 + t;
            int k = id >> 5, c4 = id & 31;
            float4 v = *(const float4*)(W + (size_t)(kk + k) * 128 + c4 * 4);
            *(float4*)&Bs[k][c4 * 4] = v;
        }
        __syncthreads();

#pragma unroll
        for (int k = 0; k < 16; k++) {
            float a[8], b[8];
            *(float4*)&a[0] = *(const float4*)&As[k][tmb];
            *(float4*)&a[4] = *(const float4*)&As[k][tmb + 4];
            *(float4*)&b[0] = *(const float4*)&Bs[k][tnb];
            *(float4*)&b[4] = *(const float4*)&Bs[k][tnb + 4];
#pragma unroll
            for (int i = 0; i < 8; i++)
#pragma unroll
                for (int j = 0; j < 8; j++)
                    acc[i][j] = fmaf(a[i], b[j], acc[i][j]);
        }
        __syncthreads();
    }

    // epilogue: convert to fp16, one 16B store of 8 halfs per row-chunk
#pragma unroll
    for (int i = 0; i < 8; i++) {
        int row = rowBase + tmb + i;
        if (row >= N) continue;
        __half2 hbuf[4];
#pragma unroll
        for (int j = 0; j < 4; j++)
            hbuf[j] = __floats2half2_rn(acc[i][2 * j], acc[i][2 * j + 1]);
        *(uint4*)(g_h + (size_t)row * 128 + tnb) = *(const uint4*)&hbuf[0];
    }
}

// ---------------------------------------------------------------------------
// CSR aggregation: one warp per dst node; fp16 gathers (256B/row).
// EPI 0: store fp32 row to g_agg.
// EPI 1: z[d] = dot(relu(row), W3) -> g_z   (fused layer-3 projection)
// ---------------------------------------------------------------------------
template <int EPI>
__global__ void __launch_bounds__(256)
k_agg(const float* __restrict__ bias, const float* __restrict__ W3, int N)
{
    int idx = blockIdx.x * blockDim.x + threadIdx.x;
    int d = idx >> 5;
    int lane = idx & 31;
    if (d >= N) return;

    const float dd = g_dinv[d];
    const int col = lane * 4;           // 4 fp16 values per lane
    const unsigned FULL = 0xffffffffu;

    // self-loop + bias
    float2 raw = *(const float2*)(g_h + (size_t)d * 128 + col);
    float2 lo = __half22float2(*(const __half2*)&raw.x);
    float2 hi = __half22float2(*(const __half2*)&raw.y);
    float4 bb = *(const float4*)(bias + col);
    float d2 = dd * dd;
    float4 acc = make_float4(fmaf(lo.x, d2, bb.x), fmaf(lo.y, d2, bb.y),
                             fmaf(hi.x, d2, bb.z), fmaf(hi.y, d2, bb.w));

    int beg = g_rowptr[d];
    int end = g_rowptr[d + 1];
    for (int p = beg; p < end; p += 32) {
        int m = end - p;
        if (m > 32) m = 32;
        int s = 0;
        float ns = 0.0f;
        if (lane < m) {
            s = g_csr_src[p + lane];
            ns = g_dinv[s];
        }
        for (int j = 0; j < m; j++) {
            int sj = __shfl_sync(FULL, s, j);
            float nj = __shfl_sync(FULL, ns, j) * dd;
            float2 r = *(const float2*)(g_h + (size_t)sj * 128 + col);
            float2 vlo = __half22float2(*(const __half2*)&r.x);
            float2 vhi = __half22float2(*(const __half2*)&r.y);
            acc.x = fmaf(vlo.x, nj, acc.x);
            acc.y = fmaf(vlo.y, nj, acc.y);
            acc.z = fmaf(vhi.x, nj, acc.z);
            acc.w = fmaf(vhi.y, nj, acc.w);
        }
    }
    if (EPI == 0) {
        *(float4*)(g_agg + (size_t)d * 128 + col) = acc;
    } else {
        acc.x = fmaxf(acc.x, 0.f); acc.y = fmaxf(acc.y, 0.f);
        acc.z = fmaxf(acc.z, 0.f); acc.w = fmaxf(acc.w, 0.f);
        float4 w = *(const float4*)(W3 + col);
        float sdot = acc.x * w.x + acc.y * w.y + acc.z * w.z + acc.w * w.w;
#pragma unroll
        for (int o = 16; o > 0; o >>= 1) sdot += __shfl_xor_sync(FULL, sdot, o);
        if (lane == 0) g_z[d] = sdot;
    }
}

// Final: out[d] = sigmoid(z[d]*dd^2 + b3 + dd * sum_in z[s]*dinv[s])
__global__ void __launch_bounds__(256)
k_agg3(const float* __restrict__ b3, float* __restrict__ out, int N)
{
    int idx = blockIdx.x * blockDim.x + threadIdx.x;
    int d = idx >> 5;
    int lane = idx & 31;
    if (d >= N) return;
    int beg = g_rowptr[d];
    int end = g_rowptr[d + 1];
    float sum = 0.0f;
    for (int p = beg + lane; p < end; p += 32) {
        int s = g_csr_src[p];
        sum = fmaf(g_z[s], g_dinv[s], sum);
    }
#pragma unroll
    for (int o = 16; o > 0; o >>= 1) sum += __shfl_xor_sync(0xffffffffu, sum, o);
    if (lane == 0) {
        float dd = g_dinv[d];
        float val = fmaf(g_z[d], dd * dd, fmaf(dd, sum, b3[0]));
        out[d] = 1.0f / (1.0f + expf(-val));
    }
}

// ---------------------------------------------------------------------------
extern "C" void kernel_launch(void* const* d_in, const int* in_sizes, int n_in,
                              void* d_out, int out_size)
{
    const float* x_i = (const float*)d_in[0];
    const float* x_j = (const float*)d_in[1];
    const void*  ei  = d_in[2];
    const float* W1 = (const float*)d_in[3];
    const float* b1 = (const float*)d_in[4];
    const float* W2 = (const float*)d_in[5];
    const float* b2 = (const float*)d_in[6];
    const float* W3 = (const float*)d_in[7];
    const float* b3 = (const float*)d_in[8];
    float* out = (float*)d_out;

    const int N = in_sizes[0] / 64;
    const int E = in_sizes[2] / 2;

    const int TB = 256;
    const int NB = (N + 1023) / 1024;
    dim3 gN((N + TB - 1) / TB);
    dim3 gE((E + TB - 1) / TB);
    dim3 gGemm((N + 63) / 64);
    dim3 gWarpN((unsigned)(((long long)N * 32 + TB - 1) / TB));

    // CSR build
    k_init<<<gN, TB>>>((const int*)ei, N);
    k_convert_count<<<gE, TB>>>(ei, E, N);
    k_scan1<<<NB, 1024>>>(N);
    k_scan2<<<1, 64>>>(NB, N);
    k_scan3<<<NB, 1024>>>(N);
    k_fill<<<gE, TB>>>(E, N);

    // layer 1
    k_gemm<0><<<gGemm, 128>>>(x_i, x_j, W1, N);
    k_agg<0><<<gWarpN, TB>>>(b1, nullptr, N);

    // layer 2 (z fused into agg epilogue)
    k_gemm<1><<<gGemm, 128>>>(nullptr, nullptr, W2, N);
    k_agg<1><<<gWarpN, TB>>>(b2, W3, N);

    // layer 3 final
    k_agg3<<<gWarpN, TB>>>(b3, out, N);
}